// round 12
// baseline (speedup 1.0000x reference)
#include <cuda_runtime.h>
#include <cuda_fp16.h>
#include <cstdint>
#include <math.h>

// Problem constants
#define HN    1024
#define EMBD  512
#define VOC   32000
#define BB    16
#define SEQ   128
#define MROWS (BB*SEQ)   // 2048
#define G4    (4*HN)     // 4096

// Scratch (device globals: allocation-free). fp16 operands stored as packed
// half2 words (unsigned) so GEMM addressing is in 32-bit "words" = 2 halves.
__device__ float    g_XG[MROWS * G4];              // [2048,4096] fp32 gate projections
__device__ unsigned g_HS[MROWS * HN/2];            // hidden states, half2 words
__device__ unsigned g_Arows[MROWS * EMBD/2];       // gathered emb rows, half2 words
__device__ unsigned g_Wih_h[G4 * EMBD/2];          // W_ih, half2 words
__device__ unsigned g_Wfc_h[(size_t)VOC * HN/2];   // W_fc, half2 words
__device__ unsigned g_Hb[2][BB * HN/2];            // h double buffer, half2 words
__device__ float    g_C[BB * HN];
// Hierarchical barrier: 8 counters, 2KB apart -> distinct L2 lines/partitions
#define NCTR 8
#define CTR_STRIDE 512                              // 512 uints = 2048 B
__device__ unsigned g_ctrs[NCTR * CTR_STRIDE];

__device__ __forceinline__ unsigned f2h2(float a, float b){
    __half2 h = __floats2half2_rn(a, b);
    return *reinterpret_cast<unsigned*>(&h);
}

// m16n8k16 fp16 MMA, fp32 accumulate.
// Slot semantics: a0=(row g, word P0), a1=(row g+8, P0), a2=(row g, P1),
// a3=(row g+8, P1); b0=(col g, P0), b1=(col g, P1). Each word = 2 consecutive
// k (half2) — packing identical on A and B; k-order free (validated R9).
#define MMA_F16(d, a0,a1,a2,a3, b0,b1) \
  asm volatile("mma.sync.aligned.m16n8k16.row.col.f32.f16.f16.f32 " \
    "{%0,%1,%2,%3}, {%4,%5,%6,%7}, {%8,%9}, {%0,%1,%2,%3};\n" \
    : "+f"(d[0]), "+f"(d[1]), "+f"(d[2]), "+f"(d[3]) \
    : "r"(a0), "r"(a1), "r"(a2), "r"(a3), "r"(b0), "r"(b1))

#define CP16(dst,src) asm volatile("cp.async.cg.shared.global [%0], [%1], 16;\n" :: "r"(dst), "l"(src))
#define CP_COMMIT()   asm volatile("cp.async.commit_group;\n")
#define CP_WAIT(n)    asm volatile("cp.async.wait_group %0;\n" :: "n"(n))

// ============================================================================
// fp32 -> fp16 conversion (grid-stride; float4 in, uint2 = 2 half2 out)
// ============================================================================
__global__ void __launch_bounds__(256) cvt_f16_kernel(
    const float4* __restrict__ in, uint2* __restrict__ out, int n4)
{
    int i = blockIdx.x * blockDim.x + threadIdx.x;
    int stride = gridDim.x * blockDim.x;
    for (; i < n4; i += stride){
        float4 v = in[i];
        uint2 u; u.x = f2h2(v.x, v.y); u.y = f2h2(v.z, v.w);
        out[i] = u;
    }
}

// Gather-convert embedding rows: out[r] = fp16(emb[tgt[r]])
__global__ void __launch_bounds__(128) gather_cvt_kernel(
    const float* __restrict__ emb, const int* __restrict__ tgt,
    unsigned* __restrict__ out)
{
    int row = blockIdx.x;
    const float4* src = (const float4*)(emb + (size_t)tgt[row] * EMBD);
    uint2* dst = (uint2*)(out + (size_t)row * (EMBD/2));
    int t = threadIdx.x;                      // 128 threads, 128 float4
    float4 v = src[t];
    uint2 u; u.x = f2h2(v.x, v.y); u.y = f2h2(v.z, v.w);
    dst[t] = u;
}

// ============================================================================
// FP16 GEMM (frozen from R9): C[M,N] = A[M,K] @ B[N,K]^T + bias0 (+bias1),
// fp32 accumulate. Operands half2-packed; Kw = K/2 words. BM=BN=128, BKW=32,
// 256 threads (8 warps, 32x64 warp tiles), 2-stage cp.async, LDS.128
// fragment loads via free k-permutation. Grid: x = M tiles (fast).
// ============================================================================
__global__ void __launch_bounds__(256) gemm_f16(
    const unsigned* __restrict__ A, const unsigned* __restrict__ B,
    const float* __restrict__ bias0, const float* __restrict__ bias1,
    float* __restrict__ C, int M, int N, int Kw)
{
    constexpr int BM=128, BN=128, BKW=32, LD=36;
    extern __shared__ unsigned smem[];
    unsigned* As = smem;                 // [2][128][36]
    unsigned* Bs = smem + 2*BM*LD;       // [2][128][36]

    const int tid  = threadIdx.x;
    const int lane = tid & 31, w = tid >> 5;
    const int bm0  = blockIdx.x * BM;
    const int bn0  = blockIdx.y * BN;
    const int mb   = (w & 3) * 32;       // warp M offset (4x2 warp grid)
    const int nb   = (w >> 2) * 64;      // warp N offset
    const int g    = lane >> 2, t4 = lane & 3;

    const unsigned* asrc[4]; unsigned adst[4];
    const unsigned* bsrc[4]; unsigned bdst[4];
    unsigned As_b = (unsigned)__cvta_generic_to_shared(As);
    unsigned Bs_b = (unsigned)__cvta_generic_to_shared(Bs);
    #pragma unroll
    for (int j=0;j<4;j++){
        int idx = tid + 256*j;
        int r = idx >> 3, c4 = idx & 7;
        asrc[j] = A + (size_t)(bm0 + r) * Kw + c4*4;
        adst[j] = As_b + (unsigned)((r*LD + c4*4) * 4);
        bsrc[j] = B + (size_t)(bn0 + r) * Kw + c4*4;
        bdst[j] = Bs_b + (unsigned)((r*LD + c4*4) * 4);
    }
    const unsigned stS = BM*LD*4;

    float acc[2][8][4];
    #pragma unroll
    for (int i=0;i<2;i++)
        #pragma unroll
        for (int j=0;j<8;j++)
            #pragma unroll
            for (int k=0;k<4;k++) acc[i][j][k]=0.f;

    const int niter = Kw / BKW;
    #pragma unroll
    for (int j=0;j<4;j++){ CP16(adst[j], asrc[j]); CP16(bdst[j], bsrc[j]); }
    CP_COMMIT();
    #pragma unroll
    for (int j=0;j<4;j++){ CP16(adst[j]+stS, asrc[j]+BKW); CP16(bdst[j]+stS, bsrc[j]+BKW); }
    CP_COMMIT();
    CP_WAIT(1);
    __syncthreads();

    for (int it=0; it<niter; it++){
        const int s = it & 1;
        const unsigned* As_ = As + s*BM*LD;
        const unsigned* Bs_ = Bs + s*BM*LD;
        #pragma unroll
        for (int kq=0; kq<2; kq++){
            uint4 a[2][2], b[8];
            #pragma unroll
            for (int mt=0; mt<2; mt++){
                const unsigned* p = As_ + (mb + mt*16 + g)*LD + t4*8 + kq*4;
                a[mt][0] = *(const uint4*)p;
                a[mt][1] = *(const uint4*)(p + 8*LD);
            }
            #pragma unroll
            for (int nt=0; nt<8; nt++)
                b[nt] = *(const uint4*)(Bs_ + (nb + nt*8 + g)*LD + t4*8 + kq*4);
            #pragma unroll
            for (int mt=0; mt<2; mt++)
                #pragma unroll
                for (int nt=0; nt<8; nt++){
                    MMA_F16(acc[mt][nt], a[mt][0].x, a[mt][1].x, a[mt][0].y, a[mt][1].y,
                            b[nt].x, b[nt].y);
                    MMA_F16(acc[mt][nt], a[mt][0].z, a[mt][1].z, a[mt][0].w, a[mt][1].w,
                            b[nt].z, b[nt].w);
                }
        }
        __syncthreads();
        if (it + 2 < niter){
            const int k0 = (it+2)*BKW;
            const unsigned so = (unsigned)s*stS;
            #pragma unroll
            for (int j=0;j<4;j++){ CP16(adst[j]+so, asrc[j]+k0); CP16(bdst[j]+so, bsrc[j]+k0); }
            CP_COMMIT();
            CP_WAIT(1);
        } else {
            CP_WAIT(0);
        }
        __syncthreads();
    }

    #pragma unroll
    for (int mt=0; mt<2; mt++){
        int row = bm0 + mb + mt*16 + g;
        #pragma unroll
        for (int nt=0; nt<8; nt++){
            int col = bn0 + nb + nt*8 + 2*t4;
            float b0v = bias0[col], b1v = bias0[col+1];
            if (bias1){ b0v += bias1[col]; b1v += bias1[col+1]; }
            float2 v0 = make_float2(acc[mt][nt][0] + b0v, acc[mt][nt][1] + b1v);
            float2 v1 = make_float2(acc[mt][nt][2] + b0v, acc[mt][nt][3] + b1v);
            *(float2*)(C + (size_t)row*N + col)     = v0;
            *(float2*)(C + (size_t)(row+8)*N + col) = v1;
        }
    }
}

// ============================================================================
// Persistent LSTM recurrence: 128 CTAs (1/SM), each CTA owns 8 hidden units.
// Barrier: arrivals fan out over 8 counters on distinct L2 lines (16 parallel
// drains each); wait = ONE thread per CTA batch-issuing all 8 counter loads
// (MLP=8, pend-mask re-issue) -> 128 pollers total (8x less line pressure
// than R10, single-hop detection unlike R11). XG prefetched before barrier.
// ============================================================================
__global__ void __launch_bounds__(256) lstm_kernel(const float* __restrict__ W_hh)
{
    constexpr int HW  = HN/2;            // 512 words per row
    constexpr int LDW = HW + 4;          // 516: conflict-free frag banks
    extern __shared__ unsigned smem_u[];
    unsigned* WsU = smem_u;              // [32][516] half2 words
    unsigned* HsU = WsU + 32*LDW;        // [16][516] half2 words
    float*    Gs  = (float*)(HsU + 16*LDW);  // [2][16][32] fp32 gate partials

    const int tid  = threadIdx.x, lane = tid & 31, w = tid >> 5;
    const int u0   = blockIdx.x * 8;
    const int gate = w & 3, half = w >> 2;
    const int g    = lane >> 2, t4 = lane & 3;

    // Load W_hh slice once, convert fp32 -> half2 words.
    #pragma unroll 4
    for (int j=0;j<32;j++){
        int idx = tid + 256*j;
        int r = idx >> 8, c4 = idx & 255;
        int grow = (r>>3)*HN + u0 + (r&7);
        float4 v = *(const float4*)(W_hh + (size_t)grow*HN + c4*4);
        uint2 u; u.x = f2h2(v.x, v.y); u.y = f2h2(v.z, v.w);
        *(uint2*)(WsU + r*LDW + c4*2) = u;
    }

    for (int t=0; t<SEQ; t++){
        // ---- XG prefetch (independent of h; hides load latency behind barrier)
        float xgi=0.f, xgf=0.f, xgg=0.f, xgo=0.f;
        int bb=0, uu=0;
        if (tid < 128){
            bb = tid >> 3; uu = tid & 7;
            size_t xb = ((size_t)bb*SEQ + t)*G4 + u0 + uu;
            xgi = __ldg(&g_XG[xb]);
            xgf = __ldg(&g_XG[xb + HN]);
            xgg = __ldg(&g_XG[xb + 2*HN]);
            xgo = __ldg(&g_XG[xb + 3*HN]);
        }

        // ---- grid barrier: spread arrivals, single-poller MLP wait
        __syncthreads();                              // prior-step writes done
        if (tid == 0){
            __threadfence();
            atomicAdd(&g_ctrs[(blockIdx.x & (NCTR-1)) * CTR_STRIDE], 1u);
            // wait: batch-poll all 8 counters, re-issue only unmet ones
            const unsigned target = (128u/NCTR) * (unsigned)(t+1);
            unsigned pend = (1u << NCTR) - 1u;
            for (;;){
                unsigned got = 0;
                #pragma unroll
                for (int i=0;i<NCTR;i++){
                    if (pend & (1u<<i)){
                        unsigned v;
                        asm volatile("ld.acquire.gpu.global.u32 %0, [%1];"
                                     : "=r"(v) : "l"(g_ctrs + i*CTR_STRIDE) : "memory");
                        if (v >= target) got |= (1u<<i);
                    }
                }
                pend &= ~got;
                if (!pend) break;
                __nanosleep(32);
            }
        }
        __syncthreads();

        // ---- copy h(t-1) half2 words -> smem (16 rows x 128 uint4)
        const unsigned* hsrc = g_Hb[t & 1];
        #pragma unroll 4
        for (int j=0;j<8;j++){
            int idx = tid + 256*j;
            int r = idx >> 7, c = idx & 127;
            *(uint4*)(HsU + r*LDW + c*4) = *(const uint4*)(hsrc + r*HW + c*4);
        }
        __syncthreads();

        // ---- gates partial over this warp's K-half (256 words = 512 halves)
        float acc0[4] = {0.f,0.f,0.f,0.f};
        float acc1[4] = {0.f,0.f,0.f,0.f};
        {
            const int ksw = half * (HW/2);
            const unsigned* hrow0 = HsU + g*LDW          + ksw + t4*8;
            const unsigned* hrow1 = HsU + (g+8)*LDW      + ksw + t4*8;
            const unsigned* wrow  = WsU + (gate*8+g)*LDW + ksw + t4*8;
            #pragma unroll 4
            for (int j=0; j<8; j++){
                const int base = j*32;
                uint4 a0  = *(const uint4*)(hrow0 + base);
                uint4 a0h = *(const uint4*)(hrow0 + base + 4);
                uint4 a1  = *(const uint4*)(hrow1 + base);
                uint4 a1h = *(const uint4*)(hrow1 + base + 4);
                uint4 b0  = *(const uint4*)(wrow  + base);
                uint4 b0h = *(const uint4*)(wrow  + base + 4);
                MMA_F16(acc0, a0.x,  a1.x,  a0.y,  a1.y,  b0.x,  b0.y);
                MMA_F16(acc1, a0.z,  a1.z,  a0.w,  a1.w,  b0.z,  b0.w);
                MMA_F16(acc0, a0h.x, a1h.x, a0h.y, a1h.y, b0h.x, b0h.y);
                MMA_F16(acc1, a0h.z, a1h.z, a0h.w, a1h.w, b0h.z, b0h.w);
            }
        }
        float* Gw = Gs + half*(16*32);
        Gw[g*32     + gate*8 + 2*t4    ] = acc0[0] + acc1[0];
        Gw[g*32     + gate*8 + 2*t4 + 1] = acc0[1] + acc1[1];
        Gw[(g+8)*32 + gate*8 + 2*t4    ] = acc0[2] + acc1[2];
        Gw[(g+8)*32 + gate*8 + 2*t4 + 1] = acc0[3] + acc1[3];
        __syncthreads();

        // ---- fused cell update: 16 batches x 8 units = 128 threads
        if (tid < 128){
            const float* G0 = Gs + bb*32;
            const float* G1 = Gs + 16*32 + bb*32;
            float vi = G0[uu]    + G1[uu]    + xgi;
            float vf = G0[8+uu]  + G1[8+uu]  + xgf;
            float vg = G0[16+uu] + G1[16+uu] + xgg;
            float vo = G0[24+uu] + G1[24+uu] + xgo;
            float iv = 1.f/(1.f + expf(-vi));
            float fv = 1.f/(1.f + expf(-vf));
            float gv = tanhf(vg);
            float ov = 1.f/(1.f + expf(-vo));
            int hi = bb*HN + u0 + uu;
            float cv = fv * g_C[hi] + iv * gv;
            float hv = ov * tanhf(cv);
            g_C[hi] = cv;
            __half hh = __float2half_rn(hv);
            ((__half*)g_Hb[(t+1) & 1])[hi] = hh;                      // next step
            ((__half*)g_HS)[((size_t)bb*SEQ + t)*HN + u0 + uu] = hh;  // logits A
        }
        // next iteration's barrier (fence + acquire) orders these writes
    }
}

// ============================================================================
// Launch
// ============================================================================
extern "C" void kernel_launch(void* const* d_in, const int* in_sizes, int n_in,
                              void* d_out, int out_size)
{
    const int*   tgt  = (const int*)  d_in[0];
    const float* h    = (const float*)d_in[1];
    const float* c    = (const float*)d_in[2];
    const float* emb  = (const float*)d_in[3];
    const float* W_ih = (const float*)d_in[4];
    const float* W_hh = (const float*)d_in[5];
    const float* b_ih = (const float*)d_in[6];
    const float* b_hh = (const float*)d_in[7];
    const float* W_fc = (const float*)d_in[8];
    const float* b_fc = (const float*)d_in[9];
    float* out = (float*)d_out;
    (void)in_sizes; (void)n_in; (void)out_size;

    void *pHb, *pC, *pCtrs, *pXG, *pHS, *pAr, *pWih, *pWfc;
    cudaGetSymbolAddress(&pHb,   g_Hb);
    cudaGetSymbolAddress(&pC,    g_C);
    cudaGetSymbolAddress(&pCtrs, g_ctrs);
    cudaGetSymbolAddress(&pXG,   g_XG);
    cudaGetSymbolAddress(&pHS,   g_HS);
    cudaGetSymbolAddress(&pAr,   g_Arows);
    cudaGetSymbolAddress(&pWih,  g_Wih_h);
    cudaGetSymbolAddress(&pWfc,  g_Wfc_h);

    cudaMemcpyAsync(pC, c, BB*HN*sizeof(float), cudaMemcpyDeviceToDevice);
    cudaMemsetAsync(pCtrs, 0, NCTR*CTR_STRIDE*sizeof(unsigned));

    const int smem_g = 2*128*36*4 * 2;                         // 73,728 B
    const int smem_r = (32*516 + 16*516)*4 + 2*16*32*4;        // 103,168 B
    cudaFuncSetAttribute(gemm_f16,    cudaFuncAttributeMaxDynamicSharedMemorySize, smem_g);
    cudaFuncSetAttribute(lstm_kernel, cudaFuncAttributeMaxDynamicSharedMemorySize, smem_r);

    // 0) conversions (fp32 -> fp16)
    cvt_f16_kernel<<<16, 256>>>((const float4*)h, (uint2*)pHb, BB*HN/4);  // h0 -> g_Hb[0]
    gather_cvt_kernel<<<MROWS, 128>>>(emb, tgt, (unsigned*)pAr);
    cvt_f16_kernel<<<1024, 256>>>((const float4*)W_ih, (uint2*)pWih, G4*EMBD/4);
    cvt_f16_kernel<<<4096, 256>>>((const float4*)W_fc, (uint2*)pWfc, VOC*(HN/4));

    // 1) XG = embrows @ W_ih^T + b_ih + b_hh   (M=2048, N=4096, Kw=256)
    dim3 g1(MROWS/128, G4/128);
    gemm_f16<<<g1, 256, smem_g>>>((const unsigned*)pAr, (const unsigned*)pWih,
                                  b_ih, b_hh, (float*)pXG, MROWS, G4, EMBD/2);

    // 2) 128-step recurrence, persistent (128 CTAs)
    lstm_kernel<<<128, 256, smem_r>>>(W_hh);

    // 3) logits = HS @ W_fc^T + b_fc           (M=2048, N=32000, Kw=512)
    dim3 g2(MROWS/128, VOC/128);
    gemm_f16<<<g2, 256, smem_g>>>((const unsigned*)pHS, (const unsigned*)pWfc,
                                  b_fc, nullptr, out, MROWS, VOC, HN/2);
}

// round 13
// speedup vs baseline: 1.0871x; 1.0871x over previous
#include <cuda_runtime.h>
#include <cuda_fp16.h>
#include <cstdint>
#include <math.h>

// Problem constants
#define HN    1024
#define EMBD  512
#define VOC   32000
#define BB    16
#define SEQ   128
#define MROWS (BB*SEQ)   // 2048
#define G4    (4*HN)     // 4096

// Scratch (device globals: allocation-free). fp16 operands stored as packed
// half2 words (unsigned) so GEMM addressing is in 32-bit "words" = 2 halves.
__device__ float    g_XG[MROWS * G4];              // [2048,4096] fp32 gate projections
__device__ unsigned g_HS[MROWS * HN/2];            // hidden states, half2 words
__device__ unsigned g_Arows[MROWS * EMBD/2];       // gathered emb rows, half2 words
__device__ unsigned g_Wih_h[G4 * EMBD/2];          // W_ih, half2 words
__device__ unsigned g_Wfc_h[(size_t)VOC * HN/2];   // W_fc, half2 words
__device__ unsigned g_Hb[2][BB * HN/2];            // h double buffer, half2 words
__device__ float    g_C[BB * HN];
// Barrier: 8 counters, 2KB apart -> distinct L2 lines/partitions
#define NCTR 8
#define CTR_STRIDE 512                              // 512 uints = 2048 B
#define NCTA_LSTM 64
__device__ unsigned g_ctrs[NCTR * CTR_STRIDE];

__device__ __forceinline__ unsigned f2h2(float a, float b){
    __half2 h = __floats2half2_rn(a, b);
    return *reinterpret_cast<unsigned*>(&h);
}

// m16n8k16 fp16 MMA, fp32 accumulate.
// Slot semantics: a0=(row g, word P0), a1=(row g+8, P0), a2=(row g, P1),
// a3=(row g+8, P1); b0=(col g, P0), b1=(col g, P1). Each word = 2 consecutive
// k (half2) — packing identical on A and B; k-order free (validated R9).
#define MMA_F16(d, a0,a1,a2,a3, b0,b1) \
  asm volatile("mma.sync.aligned.m16n8k16.row.col.f32.f16.f16.f32 " \
    "{%0,%1,%2,%3}, {%4,%5,%6,%7}, {%8,%9}, {%0,%1,%2,%3};\n" \
    : "+f"(d[0]), "+f"(d[1]), "+f"(d[2]), "+f"(d[3]) \
    : "r"(a0), "r"(a1), "r"(a2), "r"(a3), "r"(b0), "r"(b1))

#define CP16(dst,src) asm volatile("cp.async.cg.shared.global [%0], [%1], 16;\n" :: "r"(dst), "l"(src))
#define CP_COMMIT()   asm volatile("cp.async.commit_group;\n")
#define CP_WAIT(n)    asm volatile("cp.async.wait_group %0;\n" :: "n"(n))

// ============================================================================
// fp32 -> fp16 conversion (grid-stride; float4 in, uint2 = 2 half2 out)
// ============================================================================
__global__ void __launch_bounds__(256) cvt_f16_kernel(
    const float4* __restrict__ in, uint2* __restrict__ out, int n4)
{
    int i = blockIdx.x * blockDim.x + threadIdx.x;
    int stride = gridDim.x * blockDim.x;
    for (; i < n4; i += stride){
        float4 v = in[i];
        uint2 u; u.x = f2h2(v.x, v.y); u.y = f2h2(v.z, v.w);
        out[i] = u;
    }
}

// Gather-convert embedding rows: out[r] = fp16(emb[tgt[r]])
__global__ void __launch_bounds__(128) gather_cvt_kernel(
    const float* __restrict__ emb, const int* __restrict__ tgt,
    unsigned* __restrict__ out)
{
    int row = blockIdx.x;
    const float4* src = (const float4*)(emb + (size_t)tgt[row] * EMBD);
    uint2* dst = (uint2*)(out + (size_t)row * (EMBD/2));
    int t = threadIdx.x;                      // 128 threads, 128 float4
    float4 v = src[t];
    uint2 u; u.x = f2h2(v.x, v.y); u.y = f2h2(v.z, v.w);
    dst[t] = u;
}

// ============================================================================
// FP16 GEMM (frozen from R9): C[M,N] = A[M,K] @ B[N,K]^T + bias0 (+bias1),
// fp32 accumulate. Operands half2-packed; Kw = K/2 words. BM=BN=128, BKW=32,
// 256 threads (8 warps, 32x64 warp tiles), 2-stage cp.async, LDS.128
// fragment loads via free k-permutation. Grid: x = M tiles (fast).
// ============================================================================
__global__ void __launch_bounds__(256) gemm_f16(
    const unsigned* __restrict__ A, const unsigned* __restrict__ B,
    const float* __restrict__ bias0, const float* __restrict__ bias1,
    float* __restrict__ C, int M, int N, int Kw)
{
    constexpr int BM=128, BN=128, BKW=32, LD=36;
    extern __shared__ unsigned smem[];
    unsigned* As = smem;                 // [2][128][36]
    unsigned* Bs = smem + 2*BM*LD;       // [2][128][36]

    const int tid  = threadIdx.x;
    const int lane = tid & 31, w = tid >> 5;
    const int bm0  = blockIdx.x * BM;
    const int bn0  = blockIdx.y * BN;
    const int mb   = (w & 3) * 32;       // warp M offset (4x2 warp grid)
    const int nb   = (w >> 2) * 64;      // warp N offset
    const int g    = lane >> 2, t4 = lane & 3;

    const unsigned* asrc[4]; unsigned adst[4];
    const unsigned* bsrc[4]; unsigned bdst[4];
    unsigned As_b = (unsigned)__cvta_generic_to_shared(As);
    unsigned Bs_b = (unsigned)__cvta_generic_to_shared(Bs);
    #pragma unroll
    for (int j=0;j<4;j++){
        int idx = tid + 256*j;
        int r = idx >> 3, c4 = idx & 7;
        asrc[j] = A + (size_t)(bm0 + r) * Kw + c4*4;
        adst[j] = As_b + (unsigned)((r*LD + c4*4) * 4);
        bsrc[j] = B + (size_t)(bn0 + r) * Kw + c4*4;
        bdst[j] = Bs_b + (unsigned)((r*LD + c4*4) * 4);
    }
    const unsigned stS = BM*LD*4;

    float acc[2][8][4];
    #pragma unroll
    for (int i=0;i<2;i++)
        #pragma unroll
        for (int j=0;j<8;j++)
            #pragma unroll
            for (int k=0;k<4;k++) acc[i][j][k]=0.f;

    const int niter = Kw / BKW;
    #pragma unroll
    for (int j=0;j<4;j++){ CP16(adst[j], asrc[j]); CP16(bdst[j], bsrc[j]); }
    CP_COMMIT();
    #pragma unroll
    for (int j=0;j<4;j++){ CP16(adst[j]+stS, asrc[j]+BKW); CP16(bdst[j]+stS, bsrc[j]+BKW); }
    CP_COMMIT();
    CP_WAIT(1);
    __syncthreads();

    for (int it=0; it<niter; it++){
        const int s = it & 1;
        const unsigned* As_ = As + s*BM*LD;
        const unsigned* Bs_ = Bs + s*BM*LD;
        #pragma unroll
        for (int kq=0; kq<2; kq++){
            uint4 a[2][2], b[8];
            #pragma unroll
            for (int mt=0; mt<2; mt++){
                const unsigned* p = As_ + (mb + mt*16 + g)*LD + t4*8 + kq*4;
                a[mt][0] = *(const uint4*)p;
                a[mt][1] = *(const uint4*)(p + 8*LD);
            }
            #pragma unroll
            for (int nt=0; nt<8; nt++)
                b[nt] = *(const uint4*)(Bs_ + (nb + nt*8 + g)*LD + t4*8 + kq*4);
            #pragma unroll
            for (int mt=0; mt<2; mt++)
                #pragma unroll
                for (int nt=0; nt<8; nt++){
                    MMA_F16(acc[mt][nt], a[mt][0].x, a[mt][1].x, a[mt][0].y, a[mt][1].y,
                            b[nt].x, b[nt].y);
                    MMA_F16(acc[mt][nt], a[mt][0].z, a[mt][1].z, a[mt][0].w, a[mt][1].w,
                            b[nt].z, b[nt].w);
                }
        }
        __syncthreads();
        if (it + 2 < niter){
            const int k0 = (it+2)*BKW;
            const unsigned so = (unsigned)s*stS;
            #pragma unroll
            for (int j=0;j<4;j++){ CP16(adst[j]+so, asrc[j]+k0); CP16(bdst[j]+so, bsrc[j]+k0); }
            CP_COMMIT();
            CP_WAIT(1);
        } else {
            CP_WAIT(0);
        }
        __syncthreads();
    }

    #pragma unroll
    for (int mt=0; mt<2; mt++){
        int row = bm0 + mb + mt*16 + g;
        #pragma unroll
        for (int nt=0; nt<8; nt++){
            int col = bn0 + nb + nt*8 + 2*t4;
            float b0v = bias0[col], b1v = bias0[col+1];
            if (bias1){ b0v += bias1[col]; b1v += bias1[col+1]; }
            float2 v0 = make_float2(acc[mt][nt][0] + b0v, acc[mt][nt][1] + b1v);
            float2 v1 = make_float2(acc[mt][nt][2] + b0v, acc[mt][nt][3] + b1v);
            *(float2*)(C + (size_t)row*N + col)     = v0;
            *(float2*)(C + (size_t)(row+8)*N + col) = v1;
        }
    }
}

// ============================================================================
// Persistent LSTM recurrence v2: 64 CTAs x 512 threads (1/SM), each CTA owns
// 16 hidden units -> W_hh slice = 64 rows x 1024 fp16 = 128 KB smem (still
// exactly one chip-wide copy). 16 warps = 8 N-row-blocks x 2 K-halves, so
// per-warp MMA load is unchanged vs R10 (32 HMMA/step). Halving the number
// of synchronizing CTAs halves barrier arrivals, poll pressure and skew.
// Barrier = bit-exact R10 winner (8 spread counters, tid<8 pollers).
// ============================================================================
__global__ void __launch_bounds__(512) lstm_kernel(const float* __restrict__ W_hh)
{
    constexpr int HW  = HN/2;            // 512 words per row
    constexpr int LDW = HW + 4;          // 516: conflict-free frag banks
    extern __shared__ unsigned smem_u[];
    unsigned* WsU = smem_u;              // [64][516] half2 words (W_hh slice)
    unsigned* HsU = WsU + 64*LDW;        // [16][516] half2 words (h)
    float*    Gs  = (float*)(HsU + 16*LDW);  // [2][16][64] fp32 gate partials

    const int tid  = threadIdx.x, lane = tid & 31, w = tid >> 5;
    const int u0   = blockIdx.x * 16;    // this CTA's 16 hidden units
    const int rows8 = w & 7;             // warp's 8 slice rows [rows8*8 ..)
    const int half  = w >> 3;            // warp's K-half
    const int g    = lane >> 2, t4 = lane & 3;

    // Load W_hh slice once, convert fp32 -> half2 words.
    // Slice rows r = gate*16 + j  <->  global row gate*HN + u0 + j.
    // 64 rows x 256 float4 = 16384 float4; 512 threads x 32.
    #pragma unroll 4
    for (int j=0;j<32;j++){
        int idx = tid + 512*j;
        int r = idx >> 8, c4 = idx & 255;
        int grow = (r>>4)*HN + u0 + (r&15);
        float4 v = *(const float4*)(W_hh + (size_t)grow*HN + c4*4);
        uint2 u; u.x = f2h2(v.x, v.y); u.y = f2h2(v.z, v.w);
        *(uint2*)(WsU + r*LDW + c4*2) = u;
    }

    for (int t=0; t<SEQ; t++){
        // ---- XG prefetch (independent of h; hides load latency behind barrier)
        float xgi=0.f, xgf=0.f, xgg=0.f, xgo=0.f;
        int bb=0, uu=0;
        if (tid < 256){
            bb = tid >> 4; uu = tid & 15;
            size_t xb = ((size_t)bb*SEQ + t)*G4 + u0 + uu;
            xgi = __ldg(&g_XG[xb]);
            xgf = __ldg(&g_XG[xb + HN]);
            xgg = __ldg(&g_XG[xb + 2*HN]);
            xgo = __ldg(&g_XG[xb + 3*HN]);
        }

        // ---- grid barrier (R10-proven): spread arrivals, 8 pollers/CTA
        __syncthreads();                              // prior-step writes done
        if (tid == 0){
            __threadfence();
            atomicAdd(&g_ctrs[(blockIdx.x & (NCTR-1)) * CTR_STRIDE], 1u);
        }
        if (tid < NCTR){
            const unsigned target = (NCTA_LSTM/NCTR) * (unsigned)(t+1);
            unsigned v;
            for (;;){
                asm volatile("ld.acquire.gpu.global.u32 %0, [%1];"
                             : "=r"(v) : "l"(g_ctrs + tid*CTR_STRIDE) : "memory");
                if (v >= target) break;
                __nanosleep(32);
            }
        }
        __syncthreads();

        // ---- copy h(t-1) half2 words -> smem (16 rows x 128 uint4 = 2048)
        const unsigned* hsrc = g_Hb[t & 1];
        #pragma unroll 4
        for (int j=0;j<4;j++){
            int idx = tid + 512*j;
            int r = idx >> 7, c = idx & 127;
            *(uint4*)(HsU + r*LDW + c*4) = *(const uint4*)(hsrc + r*HW + c*4);
        }
        __syncthreads();

        // ---- gates partial: warp computes M=16 batches x N=8 slice rows
        //      over its K-half (256 words = 512 halves); 32 HMMA, dual accums
        float acc0[4] = {0.f,0.f,0.f,0.f};
        float acc1[4] = {0.f,0.f,0.f,0.f};
        {
            const int ksw = half * (HW/2);
            const unsigned* hrow0 = HsU + g*LDW             + ksw + t4*8;
            const unsigned* hrow1 = HsU + (g+8)*LDW         + ksw + t4*8;
            const unsigned* wrow  = WsU + (rows8*8+g)*LDW   + ksw + t4*8;
            #pragma unroll 4
            for (int j=0; j<8; j++){
                const int base = j*32;
                uint4 a0  = *(const uint4*)(hrow0 + base);
                uint4 a0h = *(const uint4*)(hrow0 + base + 4);
                uint4 a1  = *(const uint4*)(hrow1 + base);
                uint4 a1h = *(const uint4*)(hrow1 + base + 4);
                uint4 b0  = *(const uint4*)(wrow  + base);
                uint4 b0h = *(const uint4*)(wrow  + base + 4);
                MMA_F16(acc0, a0.x,  a1.x,  a0.y,  a1.y,  b0.x,  b0.y);
                MMA_F16(acc1, a0.z,  a1.z,  a0.w,  a1.w,  b0.z,  b0.w);
                MMA_F16(acc0, a0h.x, a1h.x, a0h.y, a1h.y, b0h.x, b0h.y);
                MMA_F16(acc1, a0h.z, a1h.z, a0h.w, a1h.w, b0h.z, b0h.w);
            }
        }
        float* Gw = Gs + half*(16*64);
        Gw[g*64     + rows8*8 + 2*t4    ] = acc0[0] + acc1[0];
        Gw[g*64     + rows8*8 + 2*t4 + 1] = acc0[1] + acc1[1];
        Gw[(g+8)*64 + rows8*8 + 2*t4    ] = acc0[2] + acc1[2];
        Gw[(g+8)*64 + rows8*8 + 2*t4 + 1] = acc0[3] + acc1[3];
        __syncthreads();

        // ---- fused cell update: 16 batches x 16 units = 256 threads
        if (tid < 256){
            const float* G0 = Gs + bb*64;
            const float* G1 = Gs + 16*64 + bb*64;
            float vi = G0[uu]    + G1[uu]    + xgi;
            float vf = G0[16+uu] + G1[16+uu] + xgf;
            float vg = G0[32+uu] + G1[32+uu] + xgg;
            float vo = G0[48+uu] + G1[48+uu] + xgo;
            float iv = 1.f/(1.f + expf(-vi));
            float fv = 1.f/(1.f + expf(-vf));
            float gv = tanhf(vg);
            float ov = 1.f/(1.f + expf(-vo));
            int hi = bb*HN + u0 + uu;
            float cv = fv * g_C[hi] + iv * gv;
            float hv = ov * tanhf(cv);
            g_C[hi] = cv;
            __half hh = __float2half_rn(hv);
            ((__half*)g_Hb[(t+1) & 1])[hi] = hh;                      // next step
            ((__half*)g_HS)[((size_t)bb*SEQ + t)*HN + u0 + uu] = hh;  // logits A
        }
        // next iteration's barrier (fence + acquire) orders these writes
    }
}

// ============================================================================
// Launch
// ============================================================================
extern "C" void kernel_launch(void* const* d_in, const int* in_sizes, int n_in,
                              void* d_out, int out_size)
{
    const int*   tgt  = (const int*)  d_in[0];
    const float* h    = (const float*)d_in[1];
    const float* c    = (const float*)d_in[2];
    const float* emb  = (const float*)d_in[3];
    const float* W_ih = (const float*)d_in[4];
    const float* W_hh = (const float*)d_in[5];
    const float* b_ih = (const float*)d_in[6];
    const float* b_hh = (const float*)d_in[7];
    const float* W_fc = (const float*)d_in[8];
    const float* b_fc = (const float*)d_in[9];
    float* out = (float*)d_out;
    (void)in_sizes; (void)n_in; (void)out_size;

    void *pHb, *pC, *pCtrs, *pXG, *pHS, *pAr, *pWih, *pWfc;
    cudaGetSymbolAddress(&pHb,   g_Hb);
    cudaGetSymbolAddress(&pC,    g_C);
    cudaGetSymbolAddress(&pCtrs, g_ctrs);
    cudaGetSymbolAddress(&pXG,   g_XG);
    cudaGetSymbolAddress(&pHS,   g_HS);
    cudaGetSymbolAddress(&pAr,   g_Arows);
    cudaGetSymbolAddress(&pWih,  g_Wih_h);
    cudaGetSymbolAddress(&pWfc,  g_Wfc_h);

    cudaMemcpyAsync(pC, c, BB*HN*sizeof(float), cudaMemcpyDeviceToDevice);
    cudaMemsetAsync(pCtrs, 0, NCTR*CTR_STRIDE*sizeof(unsigned));

    const int smem_g = 2*128*36*4 * 2;                         // 73,728 B
    const int smem_r = (64*516 + 16*516)*4 + 2*16*64*4;        // 173,312 B
    cudaFuncSetAttribute(gemm_f16,    cudaFuncAttributeMaxDynamicSharedMemorySize, smem_g);
    cudaFuncSetAttribute(lstm_kernel, cudaFuncAttributeMaxDynamicSharedMemorySize, smem_r);

    // 0) conversions (fp32 -> fp16)
    cvt_f16_kernel<<<16, 256>>>((const float4*)h, (uint2*)pHb, BB*HN/4);  // h0 -> g_Hb[0]
    gather_cvt_kernel<<<MROWS, 128>>>(emb, tgt, (unsigned*)pAr);
    cvt_f16_kernel<<<1024, 256>>>((const float4*)W_ih, (uint2*)pWih, G4*EMBD/4);
    cvt_f16_kernel<<<4096, 256>>>((const float4*)W_fc, (uint2*)pWfc, VOC*(HN/4));

    // 1) XG = embrows @ W_ih^T + b_ih + b_hh   (M=2048, N=4096, Kw=256)
    dim3 g1(MROWS/128, G4/128);
    gemm_f16<<<g1, 256, smem_g>>>((const unsigned*)pAr, (const unsigned*)pWih,
                                  b_ih, b_hh, (float*)pXG, MROWS, G4, EMBD/2);

    // 2) 128-step recurrence, persistent (64 CTAs x 512 threads)
    lstm_kernel<<<NCTA_LSTM, 512, smem_r>>>(W_hh);

    // 3) logits = HS @ W_fc^T + b_fc           (M=2048, N=32000, Kw=512)
    dim3 g2(MROWS/128, VOC/128);
    gemm_f16<<<g2, 256, smem_g>>>((const unsigned*)pHS, (const unsigned*)pWfc,
                                  b_fc, nullptr, out, MROWS, VOC, HN/2);
}

// round 14
// speedup vs baseline: 1.5582x; 1.4333x over previous
#include <cuda_runtime.h>
#include <cuda_fp16.h>
#include <cstdint>
#include <math.h>

// Problem constants
#define HN    1024
#define EMBD  512
#define VOC   32000
#define BB    16
#define SEQ   128
#define MROWS (BB*SEQ)   // 2048
#define G4    (4*HN)     // 4096

#define NCTA_LSTM 64
#define NCTA_ALL  148
#define NT_TILES  ((MROWS/128)*(VOC/128))   // 16 * 250 = 4000
#define NTY       (VOC/128)                 // 250 N-tiles per M-tile

// Scratch (device globals: allocation-free). fp16 operands stored as packed
// half2 words (unsigned) so GEMM addressing is in 32-bit "words" = 2 halves.
__device__ float    g_XG[MROWS * G4];              // [2048,4096] fp32 gate projections
__device__ unsigned g_HS[MROWS * HN/2];            // hidden states, T-MAJOR: row = t*16+b
__device__ unsigned g_Arows[MROWS * EMBD/2];       // gathered emb rows, half2 words
__device__ unsigned g_Wih_h[G4 * EMBD/2];          // W_ih, half2 words
__device__ unsigned g_Wfc_h[(size_t)VOC * HN/2];   // W_fc, half2 words
__device__ unsigned g_Hb[2][BB * HN/2];            // h double buffer, half2 words
__device__ float    g_C[BB * HN];
// Sync state: 8 arrive counters on distinct L2 lines; progress + work queue
#define NCTR 8
#define CTR_STRIDE 512                              // 512 uints = 2048 B
__device__ unsigned g_ctrs[NCTR * CTR_STRIDE];
__device__ unsigned g_prog[CTR_STRIDE];             // published LSTM progress
__device__ unsigned g_work[CTR_STRIDE];             // logits tile queue head

__device__ __forceinline__ unsigned f2h2(float a, float b){
    __half2 h = __floats2half2_rn(a, b);
    return *reinterpret_cast<unsigned*>(&h);
}

// m16n8k16 fp16 MMA, fp32 accumulate (slot semantics validated R9).
#define MMA_F16(d, a0,a1,a2,a3, b0,b1) \
  asm volatile("mma.sync.aligned.m16n8k16.row.col.f32.f16.f16.f32 " \
    "{%0,%1,%2,%3}, {%4,%5,%6,%7}, {%8,%9}, {%0,%1,%2,%3};\n" \
    : "+f"(d[0]), "+f"(d[1]), "+f"(d[2]), "+f"(d[3]) \
    : "r"(a0), "r"(a1), "r"(a2), "r"(a3), "r"(b0), "r"(b1))

#define CP16(dst,src) asm volatile("cp.async.cg.shared.global [%0], [%1], 16;\n" :: "r"(dst), "l"(src))
#define CP_COMMIT()   asm volatile("cp.async.commit_group;\n")
#define CP_WAIT(n)    asm volatile("cp.async.wait_group %0;\n" :: "n"(n))
#define BARX(id)      asm volatile("bar.sync %0, %1;" :: "r"(id), "r"(256) : "memory")

// ============================================================================
// fp32 -> fp16 conversion kernels (unchanged, proven)
// ============================================================================
__global__ void __launch_bounds__(256) cvt_f16_kernel(
    const float4* __restrict__ in, uint2* __restrict__ out, int n4)
{
    int i = blockIdx.x * blockDim.x + threadIdx.x;
    int stride = gridDim.x * blockDim.x;
    for (; i < n4; i += stride){
        float4 v = in[i];
        uint2 u; u.x = f2h2(v.x, v.y); u.y = f2h2(v.z, v.w);
        out[i] = u;
    }
}

__global__ void __launch_bounds__(128) gather_cvt_kernel(
    const float* __restrict__ emb, const int* __restrict__ tgt,
    unsigned* __restrict__ out)
{
    int row = blockIdx.x;
    const float4* src = (const float4*)(emb + (size_t)tgt[row] * EMBD);
    uint2* dst = (uint2*)(out + (size_t)row * (EMBD/2));
    int t = threadIdx.x;
    float4 v = src[t];
    uint2 u; u.x = f2h2(v.x, v.y); u.y = f2h2(v.z, v.w);
    dst[t] = u;
}

// ============================================================================
// Standalone FP16 GEMM (R9-proven) — used for XG only.
// ============================================================================
__global__ void __launch_bounds__(256) gemm_f16(
    const unsigned* __restrict__ A, const unsigned* __restrict__ B,
    const float* __restrict__ bias0, const float* __restrict__ bias1,
    float* __restrict__ C, int M, int N, int Kw)
{
    constexpr int BM=128, BN=128, BKW=32, LD=36;
    extern __shared__ unsigned smem[];
    unsigned* As = smem;
    unsigned* Bs = smem + 2*BM*LD;

    const int tid  = threadIdx.x;
    const int lane = tid & 31, w = tid >> 5;
    const int bm0  = blockIdx.x * BM;
    const int bn0  = blockIdx.y * BN;
    const int mb   = (w & 3) * 32;
    const int nb   = (w >> 2) * 64;
    const int g    = lane >> 2, t4 = lane & 3;

    const unsigned* asrc[4]; unsigned adst[4];
    const unsigned* bsrc[4]; unsigned bdst[4];
    unsigned As_b = (unsigned)__cvta_generic_to_shared(As);
    unsigned Bs_b = (unsigned)__cvta_generic_to_shared(Bs);
    #pragma unroll
    for (int j=0;j<4;j++){
        int idx = tid + 256*j;
        int r = idx >> 3, c4 = idx & 7;
        asrc[j] = A + (size_t)(bm0 + r) * Kw + c4*4;
        adst[j] = As_b + (unsigned)((r*LD + c4*4) * 4);
        bsrc[j] = B + (size_t)(bn0 + r) * Kw + c4*4;
        bdst[j] = Bs_b + (unsigned)((r*LD + c4*4) * 4);
    }
    const unsigned stS = BM*LD*4;

    float acc[2][8][4];
    #pragma unroll
    for (int i=0;i<2;i++)
        #pragma unroll
        for (int j=0;j<8;j++)
            #pragma unroll
            for (int k=0;k<4;k++) acc[i][j][k]=0.f;

    const int niter = Kw / BKW;
    #pragma unroll
    for (int j=0;j<4;j++){ CP16(adst[j], asrc[j]); CP16(bdst[j], bsrc[j]); }
    CP_COMMIT();
    #pragma unroll
    for (int j=0;j<4;j++){ CP16(adst[j]+stS, asrc[j]+BKW); CP16(bdst[j]+stS, bsrc[j]+BKW); }
    CP_COMMIT();
    CP_WAIT(1);
    __syncthreads();

    for (int it=0; it<niter; it++){
        const int s = it & 1;
        const unsigned* As_ = As + s*BM*LD;
        const unsigned* Bs_ = Bs + s*BM*LD;
        #pragma unroll
        for (int kq=0; kq<2; kq++){
            uint4 a[2][2], b[8];
            #pragma unroll
            for (int mt=0; mt<2; mt++){
                const unsigned* p = As_ + (mb + mt*16 + g)*LD + t4*8 + kq*4;
                a[mt][0] = *(const uint4*)p;
                a[mt][1] = *(const uint4*)(p + 8*LD);
            }
            #pragma unroll
            for (int nt=0; nt<8; nt++)
                b[nt] = *(const uint4*)(Bs_ + (nb + nt*8 + g)*LD + t4*8 + kq*4);
            #pragma unroll
            for (int mt=0; mt<2; mt++)
                #pragma unroll
                for (int nt=0; nt<8; nt++){
                    MMA_F16(acc[mt][nt], a[mt][0].x, a[mt][1].x, a[mt][0].y, a[mt][1].y,
                            b[nt].x, b[nt].y);
                    MMA_F16(acc[mt][nt], a[mt][0].z, a[mt][1].z, a[mt][0].w, a[mt][1].w,
                            b[nt].z, b[nt].w);
                }
        }
        __syncthreads();
        if (it + 2 < niter){
            const int k0 = (it+2)*BKW;
            const unsigned so = (unsigned)s*stS;
            #pragma unroll
            for (int j=0;j<4;j++){ CP16(adst[j]+so, asrc[j]+k0); CP16(bdst[j]+so, bsrc[j]+k0); }
            CP_COMMIT();
            CP_WAIT(1);
        } else {
            CP_WAIT(0);
        }
        __syncthreads();
    }

    #pragma unroll
    for (int mt=0; mt<2; mt++){
        int row = bm0 + mb + mt*16 + g;
        #pragma unroll
        for (int nt=0; nt<8; nt++){
            int col = bn0 + nb + nt*8 + 2*t4;
            float b0v = bias0[col], b1v = bias0[col+1];
            if (bias1){ b0v += bias1[col]; b1v += bias1[col+1]; }
            float2 v0 = make_float2(acc[mt][nt][0] + b0v, acc[mt][nt][1] + b1v);
            float2 v1 = make_float2(acc[mt][nt][2] + b0v, acc[mt][nt][3] + b1v);
            *(float2*)(C + (size_t)row*N + col)     = v0;
            *(float2*)(C + (size_t)(row+8)*N + col) = v1;
        }
    }
}

// ============================================================================
// Logits tile (device fn, 256 threads, named barrier barid):
//   out-perm rows: A = g_HS (t-major, row = t*16+b), B = g_Wfc_h, +b_fc.
// Identical math to gemm_f16 (Kw=512), epilogue permutes to [b][s][v].
// ============================================================================
__device__ void logits_tile(unsigned* As, int barid, int tid, int bm0, int bn0,
                            const float* __restrict__ bias0,
                            float* __restrict__ out)
{
    constexpr int BM=128, BKW=32, LD=36, Kw=HN/2;
    unsigned* Bs = As + 2*BM*LD;
    const int lane = tid & 31, w = tid >> 5;
    const int mb = (w & 3) * 32;
    const int nb = (w >> 2) * 64;
    const int g  = lane >> 2, t4 = lane & 3;

    const unsigned* asrc[4]; unsigned adst[4];
    const unsigned* bsrc[4]; unsigned bdst[4];
    unsigned As_b = (unsigned)__cvta_generic_to_shared(As);
    unsigned Bs_b = (unsigned)__cvta_generic_to_shared(Bs);
    #pragma unroll
    for (int j=0;j<4;j++){
        int idx = tid + 256*j;
        int r = idx >> 3, c4 = idx & 7;
        asrc[j] = g_HS   + (size_t)(bm0 + r) * Kw + c4*4;
        adst[j] = As_b + (unsigned)((r*LD + c4*4) * 4);
        bsrc[j] = g_Wfc_h + (size_t)(bn0 + r) * Kw + c4*4;
        bdst[j] = Bs_b + (unsigned)((r*LD + c4*4) * 4);
    }
    const unsigned stS = BM*LD*4;

    float acc[2][8][4];
    #pragma unroll
    for (int i=0;i<2;i++)
        #pragma unroll
        for (int j=0;j<8;j++)
            #pragma unroll
            for (int k=0;k<4;k++) acc[i][j][k]=0.f;

    const int niter = Kw / BKW;     // 16
    #pragma unroll
    for (int j=0;j<4;j++){ CP16(adst[j], asrc[j]); CP16(bdst[j], bsrc[j]); }
    CP_COMMIT();
    #pragma unroll
    for (int j=0;j<4;j++){ CP16(adst[j]+stS, asrc[j]+BKW); CP16(bdst[j]+stS, bsrc[j]+BKW); }
    CP_COMMIT();
    CP_WAIT(1);
    BARX(barid);

    for (int it=0; it<niter; it++){
        const int s = it & 1;
        const unsigned* As_ = As + s*BM*LD;
        const unsigned* Bs_ = Bs + s*BM*LD;
        #pragma unroll
        for (int kq=0; kq<2; kq++){
            uint4 a[2][2], b[8];
            #pragma unroll
            for (int mt=0; mt<2; mt++){
                const unsigned* p = As_ + (mb + mt*16 + g)*LD + t4*8 + kq*4;
                a[mt][0] = *(const uint4*)p;
                a[mt][1] = *(const uint4*)(p + 8*LD);
            }
            #pragma unroll
            for (int nt=0; nt<8; nt++)
                b[nt] = *(const uint4*)(Bs_ + (nb + nt*8 + g)*LD + t4*8 + kq*4);
            #pragma unroll
            for (int mt=0; mt<2; mt++)
                #pragma unroll
                for (int nt=0; nt<8; nt++){
                    MMA_F16(acc[mt][nt], a[mt][0].x, a[mt][1].x, a[mt][0].y, a[mt][1].y,
                            b[nt].x, b[nt].y);
                    MMA_F16(acc[mt][nt], a[mt][0].z, a[mt][1].z, a[mt][0].w, a[mt][1].w,
                            b[nt].z, b[nt].w);
                }
        }
        BARX(barid);
        if (it + 2 < niter){
            const int k0 = (it+2)*BKW;
            const unsigned so = (unsigned)s*stS;
            #pragma unroll
            for (int j=0;j<4;j++){ CP16(adst[j]+so, asrc[j]+k0); CP16(bdst[j]+so, bsrc[j]+k0); }
            CP_COMMIT();
            CP_WAIT(1);
        } else {
            CP_WAIT(0);
        }
        BARX(barid);
    }

    // epilogue: bias add + permuted store (row = t*16+b -> out[b][t][col])
    #pragma unroll
    for (int mt=0; mt<2; mt++){
        int row = bm0 + mb + mt*16 + g;     // row&15 == g ; row+8 -> b = g+8
        int tt  = row >> 4;
        int b0i = row & 15;
        float* orow0 = out + ((size_t)b0i*SEQ + tt) * VOC;
        float* orow1 = out + ((size_t)(b0i+8)*SEQ + tt) * VOC;
        #pragma unroll
        for (int nt=0; nt<8; nt++){
            int col = bn0 + nb + nt*8 + 2*t4;
            float bv0 = bias0[col], bv1 = bias0[col+1];
            float2 v0 = make_float2(acc[mt][nt][0] + bv0, acc[mt][nt][1] + bv1);
            float2 v1 = make_float2(acc[mt][nt][2] + bv0, acc[mt][nt][3] + bv1);
            *(float2*)(orow0 + col) = v0;
            *(float2*)(orow1 + col) = v1;
        }
    }
}

// Worker loop: pull tiles from queue (t-major order), wait on progress, run.
__device__ void worker_loop(unsigned* inst_smem, int barid, int tid,
                            volatile unsigned* smem_w,
                            const float* __restrict__ b_fc,
                            float* __restrict__ out)
{
    for (;;){
        if (tid == 0){
            unsigned wk = atomicAdd(&g_work[0], 1u);
            *smem_w = wk;
        }
        BARX(barid);
        unsigned wk = *smem_w;
        if (wk >= (unsigned)NT_TILES) break;
        int mt = wk / NTY, nt = wk % NTY;
        if (tid == 0){
            const unsigned need = 8u*mt + 8u;
            unsigned v;
            for (;;){
                asm volatile("ld.acquire.gpu.global.u32 %0, [%1];"
                             : "=r"(v) : "l"(&g_prog[0]) : "memory");
                if (v >= need) break;
                __nanosleep(256);
            }
        }
        BARX(barid);                 // also fences smem_w reuse
        logits_tile(inst_smem, barid, tid, mt*128, nt*128, b_fc, out);
    }
}

// ============================================================================
// Fused kernel: CTAs 0..63 = persistent LSTM (R13 body + progress publish,
// t-major HS store); CTAs 64..147 = logits workers (2 independent 8-warp
// GEMM instances per CTA via named barriers). After the recurrence the LSTM
// CTAs join the tile queue.
// ============================================================================
__global__ void __launch_bounds__(512) lstm_fused(
    const float* __restrict__ W_hh, const float* __restrict__ b_fc,
    float* __restrict__ out)
{
    extern __shared__ unsigned smem_u[];
    const int tid   = threadIdx.x;
    const int inst  = tid >> 8;          // GEMM instance 0/1
    const int tid256 = tid & 255;
    unsigned* inst_smem = smem_u + inst * (2*2*128*36);   // 18432 words each
    volatile unsigned* smem_w = smem_u + 2*(2*2*128*36) + inst;

    if (blockIdx.x >= NCTA_LSTM){
        worker_loop(inst_smem, 1+inst, tid256, smem_w, b_fc, out);
        return;
    }

    // ---------------- LSTM role (R13-proven body) ----------------
    constexpr int HW  = HN/2;            // 512 words per row
    constexpr int LDW = HW + 4;          // 516: conflict-free frag banks
    unsigned* WsU = smem_u;              // [64][516]
    unsigned* HsU = WsU + 64*LDW;        // [16][516]
    float*    Gs  = (float*)(HsU + 16*LDW);  // [2][16][64]

    const int lane = tid & 31, w = tid >> 5;
    const int u0    = blockIdx.x * 16;
    const int rows8 = w & 7;
    const int half  = w >> 3;
    const int g    = lane >> 2, t4 = lane & 3;

    #pragma unroll 4
    for (int j=0;j<32;j++){
        int idx = tid + 512*j;
        int r = idx >> 8, c4 = idx & 255;
        int grow = (r>>4)*HN + u0 + (r&15);
        float4 v = *(const float4*)(W_hh + (size_t)grow*HN + c4*4);
        uint2 u; u.x = f2h2(v.x, v.y); u.y = f2h2(v.z, v.w);
        *(uint2*)(WsU + r*LDW + c4*2) = u;
    }

    for (int t=0; t<SEQ; t++){
        float xgi=0.f, xgf=0.f, xgg=0.f, xgo=0.f;
        int bb=0, uu=0;
        if (tid < 256){
            bb = tid >> 4; uu = tid & 15;
            size_t xb = ((size_t)bb*SEQ + t)*G4 + u0 + uu;
            xgi = __ldg(&g_XG[xb]);
            xgf = __ldg(&g_XG[xb + HN]);
            xgg = __ldg(&g_XG[xb + 2*HN]);
            xgo = __ldg(&g_XG[xb + 3*HN]);
        }

        __syncthreads();
        if (tid == 0){
            __threadfence();
            atomicAdd(&g_ctrs[(blockIdx.x & (NCTR-1)) * CTR_STRIDE], 1u);
        }
        if (tid < NCTR){
            const unsigned target = (NCTA_LSTM/NCTR) * (unsigned)(t+1);
            unsigned v;
            for (;;){
                asm volatile("ld.acquire.gpu.global.u32 %0, [%1];"
                             : "=r"(v) : "l"(g_ctrs + tid*CTR_STRIDE) : "memory");
                if (v >= target) break;
                __nanosleep(32);
            }
        }
        __syncthreads();
        // publish progress: steps 0..t-1 now globally visible
        if (blockIdx.x == 0 && tid == 0 && t > 0){
            asm volatile("st.release.gpu.global.u32 [%0], %1;"
                         :: "l"(&g_prog[0]), "r"((unsigned)t) : "memory");
        }

        const unsigned* hsrc = g_Hb[t & 1];
        #pragma unroll 4
        for (int j=0;j<4;j++){
            int idx = tid + 512*j;
            int r = idx >> 7, c = idx & 127;
            *(uint4*)(HsU + r*LDW + c*4) = *(const uint4*)(hsrc + r*HW + c*4);
        }
        __syncthreads();

        float acc0[4] = {0.f,0.f,0.f,0.f};
        float acc1[4] = {0.f,0.f,0.f,0.f};
        {
            const int ksw = half * (HW/2);
            const unsigned* hrow0 = HsU + g*LDW             + ksw + t4*8;
            const unsigned* hrow1 = HsU + (g+8)*LDW         + ksw + t4*8;
            const unsigned* wrow  = WsU + (rows8*8+g)*LDW   + ksw + t4*8;
            #pragma unroll 4
            for (int j=0; j<8; j++){
                const int base = j*32;
                uint4 a0  = *(const uint4*)(hrow0 + base);
                uint4 a0h = *(const uint4*)(hrow0 + base + 4);
                uint4 a1  = *(const uint4*)(hrow1 + base);
                uint4 a1h = *(const uint4*)(hrow1 + base + 4);
                uint4 b0  = *(const uint4*)(wrow  + base);
                uint4 b0h = *(const uint4*)(wrow  + base + 4);
                MMA_F16(acc0, a0.x,  a1.x,  a0.y,  a1.y,  b0.x,  b0.y);
                MMA_F16(acc1, a0.z,  a1.z,  a0.w,  a1.w,  b0.z,  b0.w);
                MMA_F16(acc0, a0h.x, a1h.x, a0h.y, a1h.y, b0h.x, b0h.y);
                MMA_F16(acc1, a0h.z, a1h.z, a0h.w, a1h.w, b0h.z, b0h.w);
            }
        }
        float* Gw = Gs + half*(16*64);
        Gw[g*64     + rows8*8 + 2*t4    ] = acc0[0] + acc1[0];
        Gw[g*64     + rows8*8 + 2*t4 + 1] = acc0[1] + acc1[1];
        Gw[(g+8)*64 + rows8*8 + 2*t4    ] = acc0[2] + acc1[2];
        Gw[(g+8)*64 + rows8*8 + 2*t4 + 1] = acc0[3] + acc1[3];
        __syncthreads();

        if (tid < 256){
            const float* G0 = Gs + bb*64;
            const float* G1 = Gs + 16*64 + bb*64;
            float vi = G0[uu]    + G1[uu]    + xgi;
            float vf = G0[16+uu] + G1[16+uu] + xgf;
            float vg = G0[32+uu] + G1[32+uu] + xgg;
            float vo = G0[48+uu] + G1[48+uu] + xgo;
            float iv = 1.f/(1.f + expf(-vi));
            float fv = 1.f/(1.f + expf(-vf));
            float gv = tanhf(vg);
            float ov = 1.f/(1.f + expf(-vo));
            int hi = bb*HN + u0 + uu;
            float cv = fv * g_C[hi] + iv * gv;
            float hv = ov * tanhf(cv);
            g_C[hi] = cv;
            __half hh = __float2half_rn(hv);
            ((__half*)g_Hb[(t+1) & 1])[hi] = hh;                      // next step
            ((__half*)g_HS)[((size_t)t*BB + bb)*HN + u0 + uu] = hh;   // T-MAJOR
        }
    }

    // final arrival round -> publish prog = SEQ, then join the tile queue
    __syncthreads();
    if (tid == 0){
        __threadfence();
        atomicAdd(&g_ctrs[(blockIdx.x & (NCTR-1)) * CTR_STRIDE], 1u);
    }
    if (blockIdx.x == 0){
        if (tid < NCTR){
            const unsigned target = (NCTA_LSTM/NCTR) * (unsigned)(SEQ+1);
            unsigned v;
            for (;;){
                asm volatile("ld.acquire.gpu.global.u32 %0, [%1];"
                             : "=r"(v) : "l"(g_ctrs + tid*CTR_STRIDE) : "memory");
                if (v >= target) break;
                __nanosleep(32);
            }
        }
        __syncthreads();
        if (tid == 0){
            asm volatile("st.release.gpu.global.u32 [%0], %1;"
                         :: "l"(&g_prog[0]), "r"((unsigned)SEQ) : "memory");
        }
    }
    __syncthreads();
    worker_loop(inst_smem, 1+inst, tid256, smem_w, b_fc, out);
}

// ============================================================================
// Launch
// ============================================================================
extern "C" void kernel_launch(void* const* d_in, const int* in_sizes, int n_in,
                              void* d_out, int out_size)
{
    const int*   tgt  = (const int*)  d_in[0];
    const float* h    = (const float*)d_in[1];
    const float* c    = (const float*)d_in[2];
    const float* emb  = (const float*)d_in[3];
    const float* W_ih = (const float*)d_in[4];
    const float* W_hh = (const float*)d_in[5];
    const float* b_ih = (const float*)d_in[6];
    const float* b_hh = (const float*)d_in[7];
    const float* W_fc = (const float*)d_in[8];
    const float* b_fc = (const float*)d_in[9];
    float* out = (float*)d_out;
    (void)in_sizes; (void)n_in; (void)out_size;

    void *pHb, *pC, *pCtrs, *pProg, *pWork, *pAr, *pWih, *pWfc;
    cudaGetSymbolAddress(&pHb,   g_Hb);
    cudaGetSymbolAddress(&pC,    g_C);
    cudaGetSymbolAddress(&pCtrs, g_ctrs);
    cudaGetSymbolAddress(&pProg, g_prog);
    cudaGetSymbolAddress(&pWork, g_work);
    cudaGetSymbolAddress(&pAr,   g_Arows);
    cudaGetSymbolAddress(&pWih,  g_Wih_h);
    cudaGetSymbolAddress(&pWfc,  g_Wfc_h);
    void* pXG; cudaGetSymbolAddress(&pXG, g_XG);

    cudaMemcpyAsync(pC, c, BB*HN*sizeof(float), cudaMemcpyDeviceToDevice);
    cudaMemsetAsync(pCtrs, 0, NCTR*CTR_STRIDE*sizeof(unsigned));
    cudaMemsetAsync(pProg, 0, sizeof(unsigned));
    cudaMemsetAsync(pWork, 0, sizeof(unsigned));

    const int smem_g = 2*128*36*4 * 2;                    // 73,728 B
    const int smem_f = (64*516 + 16*516)*4 + 2*16*64*4;   // 173,312 B
    cudaFuncSetAttribute(gemm_f16,   cudaFuncAttributeMaxDynamicSharedMemorySize, smem_g);
    cudaFuncSetAttribute(lstm_fused, cudaFuncAttributeMaxDynamicSharedMemorySize, smem_f);

    // 0) conversions (fp32 -> fp16)
    cvt_f16_kernel<<<16, 256>>>((const float4*)h, (uint2*)pHb, BB*HN/4);  // h0 -> g_Hb[0]
    gather_cvt_kernel<<<MROWS, 128>>>(emb, tgt, (unsigned*)pAr);
    cvt_f16_kernel<<<1024, 256>>>((const float4*)W_ih, (uint2*)pWih, G4*EMBD/4);
    cvt_f16_kernel<<<4096, 256>>>((const float4*)W_fc, (uint2*)pWfc, VOC*(HN/4));

    // 1) XG = embrows @ W_ih^T + b_ih + b_hh   (M=2048, N=4096, Kw=256)
    dim3 g1(MROWS/128, G4/128);
    gemm_f16<<<g1, 256, smem_g>>>((const unsigned*)pAr, (const unsigned*)pWih,
                                  b_ih, b_hh, (float*)pXG, MROWS, G4, EMBD/2);

    // 2+3) fused: 64 LSTM CTAs + 84 logits-worker CTAs; LSTM CTAs join the
    //      logits tile queue after the recurrence.
    lstm_fused<<<NCTA_ALL, 512, smem_f>>>(W_hh, b_fc, out);
}